// round 1
// baseline (speedup 1.0000x reference)
#include <cuda_runtime.h>
#include <cstdint>

#define FULL 0xffffffffu

constexpr int B_  = 16;
constexpr int N_  = 4096;
constexpr int NP_ = 1024;
constexpr int K_  = 32;
constexpr int CIN = 128;
constexpr int CG  = 131;   // 3 + 128
constexpr int C_  = 256;
constexpr int H_  = 4;
constexpr int D_  = 64;
constexpr int TC  = 768;   // 3*C
constexpr int RPB = 8;     // rows per block in mlp kernel

// scratch (device globals: allocation-free rule)
__device__ int   g_idx_buf[B_ * NP_ * K_];
__device__ float g_feat_buf[B_ * NP_ * C_];

extern __shared__ unsigned char dynsm[];

// ---------------- packed f32x2 helpers (B300: FFMA 3-reg is half-rate; f32x2 doubles MAC/issue)
__device__ __forceinline__ unsigned long long pk2(float a, float b) {
    unsigned long long r;
    asm("mov.b64 %0, {%1,%2};" : "=l"(r) : "f"(a), "f"(b));
    return r;
}
__device__ __forceinline__ void upk2(unsigned long long v, float& a, float& b) {
    asm("mov.b64 {%0,%1}, %2;" : "=f"(a), "=f"(b) : "l"(v));
}
__device__ __forceinline__ void fma2(unsigned long long& d, unsigned long long a, unsigned long long b) {
    asm("fma.rn.f32x2 %0, %1, %2, %3;" : "=l"(d) : "l"(a), "l"(b), "l"(d));
}

// ============================================================================
// K1: KNN. One warp per query. Score = ||x||^2 - 2 p.x  (same ranking as ref d2).
// Warp keeps 32 best (one per lane), max-replacement with cached warp-argmax.
// Downstream is permutation-invariant in the K neighbors, so only the set matters.
// ============================================================================
__global__ void __launch_bounds__(256) knn_kernel(const float* __restrict__ xyz,
                                                  const float* __restrict__ nxyz) {
    float4* pts = reinterpret_cast<float4*>(dynsm);  // 4096 x {x,y,z,|.|^2} = 64KB
    const int b = blockIdx.y;
    const float* xb = xyz + (long)b * N_ * 3;
    for (int j = threadIdx.x; j < N_; j += 256) {
        float x = xb[j * 3 + 0], y = xb[j * 3 + 1], z = xb[j * 3 + 2];
        pts[j] = make_float4(x, y, z, x * x + y * y + z * z);
    }
    __syncthreads();

    const int warp = threadIdx.x >> 5, lane = threadIdx.x & 31;
    const int p = blockIdx.x * 8 + warp;
    const float* q = nxyz + ((long)b * NP_ + p) * 3;
    const float qx = q[0], qy = q[1], qz = q[2];

    float4 c0 = pts[lane];
    float bestd = c0.w - 2.f * (qx * c0.x + qy * c0.y + qz * c0.z);
    int besti = lane;

    float curmax;
    int maxlane;
    {
        float v = bestd; int l = lane;
#pragma unroll
        for (int o = 16; o; o >>= 1) {
            float v2 = __shfl_xor_sync(FULL, v, o);
            int l2 = __shfl_xor_sync(FULL, l, o);
            if (v2 > v || (v2 == v && l2 < l)) { v = v2; l = l2; }
        }
        curmax = v; maxlane = l;
    }

    for (int j0 = K_; j0 < N_; j0 += K_) {
        float4 c = pts[j0 + lane];
        float d = c.w - 2.f * (qx * c.x + qy * c.y + qz * c.z);
        unsigned mset = __ballot_sync(FULL, d < curmax);
        while (mset) {
            int src = __ffs(mset) - 1;
            mset &= mset - 1;
            float cd = __shfl_sync(FULL, d, src);
            if (cd < curmax) {            // uniform predicate
                if (lane == maxlane) { bestd = cd; besti = j0 + src; }
                float v = bestd; int l = lane;
#pragma unroll
                for (int o = 16; o; o >>= 1) {
                    float v2 = __shfl_xor_sync(FULL, v, o);
                    int l2 = __shfl_xor_sync(FULL, l, o);
                    if (v2 > v || (v2 == v && l2 < l)) { v = v2; l = l2; }
                }
                curmax = v; maxlane = l;
            }
        }
    }
    g_idx_buf[((long)b * NP_ + p) * K_ + lane] = besti;
}

// ============================================================================
// K2: fused group -> LN -> QKV -> (degenerate) attention -> proj + dense branch.
// One block (256 thr) per (b,p) group. x stored transposed xsT[i][r] so row
// pairs load as LDS.64 and accumulate with fma.rn.f32x2.
// ============================================================================
struct SmemAttn {
    float xsT[CG][34];      // LN'd grouped features, transposed (pitch 34 -> 8B-aligned rows)
    float kbufT[C_][33];    // k matrix [col][row], pitch 33 -> conflict-free lane reads
    float qm[C_];           // max over K of q, per column
    float gmax[CG + 1];     // max over K of raw gf (dense branch)
    float attnw[H_][K_];    // softmax weights
    float sat[C_];          // attention output (pre-proj)
    int   nidx[K_];
    float q3[3];
};

__global__ void __launch_bounds__(256, 3) attn_kernel(
    const float* __restrict__ xyz, const float* __restrict__ nxyz,
    const float* __restrict__ featin, const float* __restrict__ wqkv,
    const float* __restrict__ projw, const float* __restrict__ projb,
    const float* __restrict__ densew, const float* __restrict__ denseb,
    const float* __restrict__ n1g, const float* __restrict__ n1b) {
    SmemAttn& s = *reinterpret_cast<SmemAttn*>(dynsm);
    const int t = threadIdx.x;
    const int grp = blockIdx.x;
    const int b = grp >> 10, p = grp & 1023;

    if (t < K_) s.nidx[t] = g_idx_buf[grp * K_ + t];
    if (t < 3) s.q3[t] = nxyz[((long)b * NP_ + p) * 3 + t];
    __syncthreads();

    // gather: relative xyz (cols 0..2) + features (cols 3..130)
    if (t < K_) {
        int j = s.nidx[t];
        const float* xp = xyz + ((long)b * N_ + j) * 3;
        s.xsT[0][t] = xp[0] - s.q3[0];
        s.xsT[1][t] = xp[1] - s.q3[1];
        s.xsT[2][t] = xp[2] - s.q3[2];
    }
    for (int e = t; e < K_ * CIN; e += 256) {
        int r = e >> 7, i = e & 127;
        s.xsT[3 + i][r] = featin[((long)b * N_ + s.nidx[r]) * CIN + i];
    }
    __syncthreads();

    // max over K of raw gf (dense branch input) before LN overwrites
    if (t < CG) {
        float m = s.xsT[t][0];
#pragma unroll
        for (int r = 1; r < K_; ++r) m = fmaxf(m, s.xsT[t][r]);
        s.gmax[t] = m;
    }
    __syncthreads();

    // LayerNorm each of the 32 rows over CG=131, eps=1e-3 (two-pass, ref-faithful)
    if (t < K_) {
        float sum = 0.f;
        for (int i = 0; i < CG; ++i) sum += s.xsT[i][t];
        float m = sum * (1.f / CG);
        float vs = 0.f;
        for (int i = 0; i < CG; ++i) { float d = s.xsT[i][t] - m; vs += d * d; }
        float rs = rsqrtf(vs * (1.f / CG) + 1e-3f);
        for (int i = 0; i < CG; ++i)
            s.xsT[i][t] = (s.xsT[i][t] - m) * rs * n1g[i] + n1b[i];
    }
    __syncthreads();

    unsigned long long acc2[16];

    // ---- Q pass: thread t owns q column t; only column-max over rows survives
    {
#pragma unroll
        for (int rp = 0; rp < 16; ++rp) acc2[rp] = 0ull;
        const float* wcol = wqkv + t;
#pragma unroll 4
        for (int i = 0; i < CG; ++i) {
            float w = wcol[(long)i * TC];
            unsigned long long w2 = pk2(w, w);
            const unsigned long long* xr = reinterpret_cast<const unsigned long long*>(s.xsT[i]);
#pragma unroll
            for (int rp = 0; rp < 16; ++rp) fma2(acc2[rp], xr[rp], w2);
        }
        float mx = -1e30f;
#pragma unroll
        for (int rp = 0; rp < 16; ++rp) {
            float a, bv; upk2(acc2[rp], a, bv);
            mx = fmaxf(mx, fmaxf(a, bv));
        }
        s.qm[t] = mx;
    }

    // ---- K pass: thread t owns k column t; stash rows for the logit reduction
    {
#pragma unroll
        for (int rp = 0; rp < 16; ++rp) acc2[rp] = 0ull;
        const float* wcol = wqkv + C_ + t;
#pragma unroll 4
        for (int i = 0; i < CG; ++i) {
            float w = wcol[(long)i * TC];
            unsigned long long w2 = pk2(w, w);
            const unsigned long long* xr = reinterpret_cast<const unsigned long long*>(s.xsT[i]);
#pragma unroll
            for (int rp = 0; rp < 16; ++rp) fma2(acc2[rp], xr[rp], w2);
        }
#pragma unroll
        for (int rp = 0; rp < 16; ++rp) {
            float a, bv; upk2(acc2[rp], a, bv);
            s.kbufT[t][2 * rp] = a;
            s.kbufT[t][2 * rp + 1] = bv;
        }
    }
    __syncthreads();

    // ---- logits + softmax: warp h (t<128), lane = row r
    if (t < 128) {
        int h = t >> 5, r = t & 31;
        float acc = 0.f;
#pragma unroll 8
        for (int d = 0; d < D_; ++d) acc += s.qm[h * D_ + d] * s.kbufT[h * D_ + d][r];
        acc *= 0.0625f;  // C^-0.5 = 1/16
        float mx = acc;
#pragma unroll
        for (int o = 16; o; o >>= 1) mx = fmaxf(mx, __shfl_xor_sync(FULL, mx, o));
        float e = expf(acc - mx);
        float ss = e;
#pragma unroll
        for (int o = 16; o; o >>= 1) ss += __shfl_xor_sync(FULL, ss, o);
        s.attnw[h][r] = e / ss;
    }
    __syncthreads();

    // ---- V pass + attention-weighted sum over rows
    {
#pragma unroll
        for (int rp = 0; rp < 16; ++rp) acc2[rp] = 0ull;
        const float* wcol = wqkv + 2 * C_ + t;
#pragma unroll 4
        for (int i = 0; i < CG; ++i) {
            float w = wcol[(long)i * TC];
            unsigned long long w2 = pk2(w, w);
            const unsigned long long* xr = reinterpret_cast<const unsigned long long*>(s.xsT[i]);
#pragma unroll
            for (int rp = 0; rp < 16; ++rp) fma2(acc2[rp], xr[rp], w2);
        }
        int h = t >> 6;
        float o = 0.f;
#pragma unroll
        for (int rp = 0; rp < 16; ++rp) {
            float a, bv; upk2(acc2[rp], a, bv);
            o += s.attnw[h][2 * rp] * a + s.attnw[h][2 * rp + 1] * bv;
        }
        s.sat[t] = o;
    }
    __syncthreads();

    // ---- proj (relu) + dense branch (relu) -> feat
    float pa = 0.f;
#pragma unroll 4
    for (int i = 0; i < C_; ++i) pa += s.sat[i] * projw[i * C_ + t];
    pa = fmaxf(pa + projb[t], 0.f);
    float da = 0.f;
#pragma unroll 4
    for (int i = 0; i < CG; ++i) da += s.gmax[i] * densew[i * C_ + t];
    da = fmaxf(da + denseb[t], 0.f);
    g_feat_buf[(long)grp * C_ + t] = pa + da;
}

// ============================================================================
// K3: LN2 -> fc1(relu) -> fc2 -> +feat. 8 rows per block so fc weights are
// reloaded 2048x (not 16384x) from L2; rows packed in f32x2 pairs.
// ============================================================================
__global__ void __launch_bounds__(256) mlp_kernel(
    const float* __restrict__ fc1w, const float* __restrict__ fc1b,
    const float* __restrict__ fc2w, const float* __restrict__ fc2b,
    const float* __restrict__ n2g, const float* __restrict__ n2b,
    float* __restrict__ out) {
    __shared__ float fbuf[RPB][C_];
    __shared__ float lnT[C_][RPB + 2];      // pitch 10 floats -> 8B-aligned rows
    __shared__ float hT[2 * C_][RPB + 2];
    const int t = threadIdx.x;
    const long row0 = (long)blockIdx.x * RPB;

    for (int e = t; e < RPB * C_; e += 256) {
        int r = e >> 8, i = e & 255;
        fbuf[r][i] = g_feat_buf[(row0 + r) * C_ + i];
    }
    __syncthreads();

    // LN per row: warp w handles row w
    {
        int w = t >> 5, l = t & 31;
        float v[8], s0 = 0.f;
#pragma unroll
        for (int k2 = 0; k2 < 8; ++k2) { v[k2] = fbuf[w][l + 32 * k2]; s0 += v[k2]; }
#pragma unroll
        for (int o = 16; o; o >>= 1) s0 += __shfl_xor_sync(FULL, s0, o);
        float m = s0 * (1.f / C_);
        float q = 0.f;
#pragma unroll
        for (int k2 = 0; k2 < 8; ++k2) { float d = v[k2] - m; q += d * d; }
#pragma unroll
        for (int o = 16; o; o >>= 1) q += __shfl_xor_sync(FULL, q, o);
        float rs = rsqrtf(q * (1.f / C_) + 1e-3f);
#pragma unroll
        for (int k2 = 0; k2 < 8; ++k2) {
            int i = l + 32 * k2;
            lnT[i][w] = (v[k2] - m) * rs * n2g[i] + n2b[i];
        }
    }
    __syncthreads();

    // fc1: thread t does cols t and t+256, 8 rows packed as 4 f32x2 accs
    for (int jj = 0; jj < 2; ++jj) {
        int j = t + jj * C_;
        unsigned long long acc[4] = {0ull, 0ull, 0ull, 0ull};
#pragma unroll 4
        for (int i = 0; i < C_; ++i) {
            float w = fc1w[i * (2 * C_) + j];
            unsigned long long w2 = pk2(w, w);
            const unsigned long long* lr = reinterpret_cast<const unsigned long long*>(lnT[i]);
#pragma unroll
            for (int rp = 0; rp < 4; ++rp) fma2(acc[rp], lr[rp], w2);
        }
        float bb = fc1b[j];
#pragma unroll
        for (int rp = 0; rp < 4; ++rp) {
            float a, bv; upk2(acc[rp], a, bv);
            hT[j][2 * rp]     = fmaxf(a + bb, 0.f);
            hT[j][2 * rp + 1] = fmaxf(bv + bb, 0.f);
        }
    }
    __syncthreads();

    // fc2: thread t does col t over 512, 8 rows packed; + bias + residual
    {
        unsigned long long acc[4] = {0ull, 0ull, 0ull, 0ull};
#pragma unroll 4
        for (int j = 0; j < 2 * C_; ++j) {
            float w = fc2w[j * C_ + t];
            unsigned long long w2 = pk2(w, w);
            const unsigned long long* hr = reinterpret_cast<const unsigned long long*>(hT[j]);
#pragma unroll
            for (int rp = 0; rp < 4; ++rp) fma2(acc[rp], hr[rp], w2);
        }
        float bb = fc2b[t];
#pragma unroll
        for (int rp = 0; rp < 4; ++rp) {
            float a, bv; upk2(acc[rp], a, bv);
            out[(row0 + 2 * rp) * C_ + t]     = a + bb + fbuf[2 * rp][t];
            out[(row0 + 2 * rp + 1) * C_ + t] = bv + bb + fbuf[2 * rp + 1][t];
        }
    }
}

// ============================================================================
extern "C" void kernel_launch(void* const* d_in, const int* in_sizes, int n_in,
                              void* d_out, int out_size) {
    const float* xyz    = (const float*)d_in[0];
    const float* nxyz   = (const float*)d_in[1];
    const float* featin = (const float*)d_in[2];
    const float* wqkv   = (const float*)d_in[3];
    const float* projw  = (const float*)d_in[4];
    const float* projb  = (const float*)d_in[5];
    const float* densew = (const float*)d_in[6];
    const float* denseb = (const float*)d_in[7];
    const float* fc1w   = (const float*)d_in[8];
    const float* fc1b   = (const float*)d_in[9];
    const float* fc2w   = (const float*)d_in[10];
    const float* fc2b   = (const float*)d_in[11];
    const float* n1g    = (const float*)d_in[12];
    const float* n1b    = (const float*)d_in[13];
    const float* n2g    = (const float*)d_in[14];
    const float* n2b    = (const float*)d_in[15];
    float* out = (float*)d_out;

    (void)in_sizes; (void)n_in; (void)out_size;

    const int knn_smem = N_ * (int)sizeof(float4);          // 64 KB
    const int attn_smem = (int)sizeof(SmemAttn);            // ~54.8 KB
    cudaFuncSetAttribute(knn_kernel, cudaFuncAttributeMaxDynamicSharedMemorySize, knn_smem);
    cudaFuncSetAttribute(attn_kernel, cudaFuncAttributeMaxDynamicSharedMemorySize, attn_smem);

    knn_kernel<<<dim3(NP_ / 8, B_), 256, knn_smem>>>(xyz, nxyz);
    attn_kernel<<<B_ * NP_, 256, attn_smem>>>(xyz, nxyz, featin, wqkv, projw, projb,
                                              densew, denseb, n1g, n1b);
    mlp_kernel<<<B_ * NP_ / RPB, 256>>>(fc1w, fc1b, fc2w, fc2b, n2g, n2b, out);
}

// round 2
// speedup vs baseline: 1.3231x; 1.3231x over previous
#include <cuda_runtime.h>
#include <cstdint>

typedef unsigned long long ull;
#define FULL 0xffffffffu

constexpr int B_  = 16;
constexpr int N_  = 4096;
constexpr int NP_ = 1024;
constexpr int K_  = 32;
constexpr int CIN = 128;
constexpr int CG  = 131;   // 3 + 128
constexpr int C_  = 256;
constexpr int H_  = 4;
constexpr int D_  = 64;
constexpr int TC  = 768;   // 3*C
constexpr int RPB = 16;    // rows per block in mlp kernel

// scratch (device globals: allocation-free rule)
__device__ int   g_idx_buf[B_ * NP_ * K_];
__device__ float g_feat_buf[B_ * NP_ * C_];

extern __shared__ unsigned char dynsm[];

// ---------------- packed f32x2 helpers
__device__ __forceinline__ ull pk2(float a, float b) {
    ull r;
    asm("mov.b64 %0, {%1,%2};" : "=l"(r) : "f"(a), "f"(b));
    return r;
}
__device__ __forceinline__ void upk2(ull v, float& a, float& b) {
    asm("mov.b64 {%0,%1}, %2;" : "=f"(a), "=f"(b) : "l"(v));
}
__device__ __forceinline__ void fma2(ull& d, ull a, ull b) {
    asm("fma.rn.f32x2 %0, %1, %2, %3;" : "=l"(d) : "l"(a), "l"(b), "l"(d));
}

// ============================================================================
// K1: KNN. One warp per query, max-replacement top-32 (set-only; downstream is
// permutation invariant in neighbors).
// ============================================================================
__global__ void __launch_bounds__(256) knn_kernel(const float* __restrict__ xyz,
                                                  const float* __restrict__ nxyz) {
    float4* pts = reinterpret_cast<float4*>(dynsm);  // 4096 x {x,y,z,|.|^2}
    const int b = blockIdx.y;
    const float* xb = xyz + (long)b * N_ * 3;
    for (int j = threadIdx.x; j < N_; j += 256) {
        float x = xb[j * 3 + 0], y = xb[j * 3 + 1], z = xb[j * 3 + 2];
        pts[j] = make_float4(x, y, z, x * x + y * y + z * z);
    }
    __syncthreads();

    const int warp = threadIdx.x >> 5, lane = threadIdx.x & 31;
    const int p = blockIdx.x * 8 + warp;
    const float* q = nxyz + ((long)b * NP_ + p) * 3;
    const float qx = q[0], qy = q[1], qz = q[2];

    float4 c0 = pts[lane];
    float bestd = c0.w - 2.f * (qx * c0.x + qy * c0.y + qz * c0.z);
    int besti = lane;

    float curmax;
    int maxlane;
    {
        float v = bestd; int l = lane;
#pragma unroll
        for (int o = 16; o; o >>= 1) {
            float v2 = __shfl_xor_sync(FULL, v, o);
            int l2 = __shfl_xor_sync(FULL, l, o);
            if (v2 > v || (v2 == v && l2 < l)) { v = v2; l = l2; }
        }
        curmax = v; maxlane = l;
    }

    for (int j0 = K_; j0 < N_; j0 += K_) {
        float4 c = pts[j0 + lane];
        float d = c.w - 2.f * (qx * c.x + qy * c.y + qz * c.z);
        unsigned mset = __ballot_sync(FULL, d < curmax);
        while (mset) {
            int src = __ffs(mset) - 1;
            mset &= mset - 1;
            float cd = __shfl_sync(FULL, d, src);
            if (cd < curmax) {
                if (lane == maxlane) { bestd = cd; besti = j0 + src; }
                float v = bestd; int l = lane;
#pragma unroll
                for (int o = 16; o; o >>= 1) {
                    float v2 = __shfl_xor_sync(FULL, v, o);
                    int l2 = __shfl_xor_sync(FULL, l, o);
                    if (v2 > v || (v2 == v && l2 < l)) { v = v2; l = l2; }
                }
                curmax = v; maxlane = l;
            }
        }
    }
    g_idx_buf[((long)b * NP_ + p) * K_ + lane] = besti;
}

// ============================================================================
// K2: fused group -> LN -> QKV (single fused pass) -> attention -> proj+dense.
// ============================================================================
struct SmemAttn {
    float xsT[CG][34];      // LN'd grouped features, transposed (8B-aligned rows)
    float kbufT[C_][34];    // k matrix [col][row]
    float qm[C_];           // column-max of q
    float gmax[CG + 1];     // max over K of raw gf
    float attnw[H_][K_];    // softmax weights
    float sat[C_];          // attention output (pre-proj)
    float tmp2[2 * C_];     // proj / dense partial results
    int   nidx[K_];
    float q3[3];
};

__global__ void __launch_bounds__(256, 2) attn_kernel(
    const float* __restrict__ xyz, const float* __restrict__ nxyz,
    const float* __restrict__ featin, const float* __restrict__ wqkv,
    const float* __restrict__ projw, const float* __restrict__ projb,
    const float* __restrict__ densew, const float* __restrict__ denseb,
    const float* __restrict__ n1g, const float* __restrict__ n1b) {
    SmemAttn& s = *reinterpret_cast<SmemAttn*>(dynsm);
    const int t = threadIdx.x;
    const int grp = blockIdx.x;
    const int b = grp >> 10, p = grp & 1023;

    if (t < K_) s.nidx[t] = g_idx_buf[grp * K_ + t];
    if (t < 3) s.q3[t] = nxyz[((long)b * NP_ + p) * 3 + t];
    __syncthreads();

    // gather: relative xyz (cols 0..2) + features (cols 3..130)
    if (t < K_) {
        int j = s.nidx[t];
        const float* xp = xyz + ((long)b * N_ + j) * 3;
        s.xsT[0][t] = xp[0] - s.q3[0];
        s.xsT[1][t] = xp[1] - s.q3[1];
        s.xsT[2][t] = xp[2] - s.q3[2];
    }
    for (int e = t; e < K_ * CIN; e += 256) {
        int r = e >> 7, i = e & 127;
        s.xsT[3 + i][r] = featin[((long)b * N_ + s.nidx[r]) * CIN + i];
    }
    __syncthreads();

    // max over K of raw gf (dense branch) before LN overwrites
    if (t < CG) {
        float m = s.xsT[t][0];
#pragma unroll
        for (int r = 1; r < K_; ++r) m = fmaxf(m, s.xsT[t][r]);
        s.gmax[t] = m;
    }
    __syncthreads();

    // LayerNorm over CG=131 per row; warp w handles rows w, w+8, w+16, w+24
    {
        const int w = t >> 5, l = t & 31;
        for (int rr = 0; rr < 4; ++rr) {
            const int r = w + 8 * rr;
            float v[5];
            int kn = 0;
            float sum = 0.f;
            for (int ii = l; ii < CG; ii += 32) { v[kn] = s.xsT[ii][r]; sum += v[kn]; ++kn; }
#pragma unroll
            for (int o = 16; o; o >>= 1) sum += __shfl_xor_sync(FULL, sum, o);
            const float m = sum * (1.f / CG);
            float qv = 0.f;
            for (int k = 0; k < kn; ++k) { float d = v[k] - m; qv += d * d; }
#pragma unroll
            for (int o = 16; o; o >>= 1) qv += __shfl_xor_sync(FULL, qv, o);
            const float rs = rsqrtf(qv * (1.f / CG) + 1e-3f);
            kn = 0;
            for (int ii = l; ii < CG; ii += 32) {
                s.xsT[ii][r] = (v[kn] - m) * rs * n1g[ii] + n1b[ii];
                ++kn;
            }
        }
    }
    __syncthreads();

    // ---- fused Q/K/V pass: thread t owns column t of each of q,k,v.
    ull aq[16], ak[16], av[16];
#pragma unroll
    for (int rp = 0; rp < 16; ++rp) { aq[rp] = 0ull; ak[rp] = 0ull; av[rp] = 0ull; }
    {
        const float* wq = wqkv + t;
        const float* wk = wq + C_;
        const float* wv = wq + 2 * C_;
        float cq = wq[0], ck = wk[0], cv = wv[0];
#pragma unroll 1
        for (int i = 0; i < CG; ++i) {
            const int inx = (i + 1 < CG) ? i + 1 : i;          // prefetch next weights
            const float nq = wq[(long)inx * TC];
            const float nk = wk[(long)inx * TC];
            const float nv = wv[(long)inx * TC];
            const ull q2 = pk2(cq, cq), k2 = pk2(ck, ck), v2 = pk2(cv, cv);
            const ull* xr = reinterpret_cast<const ull*>(s.xsT[i]);
#pragma unroll
            for (int rp = 0; rp < 16; ++rp) {
                const ull x = xr[rp];
                fma2(aq[rp], x, q2);
                fma2(ak[rp], x, k2);
                fma2(av[rp], x, v2);
            }
            cq = nq; ck = nk; cv = nv;
        }
    }
    // q column max
    {
        float mx = -1e30f;
#pragma unroll
        for (int rp = 0; rp < 16; ++rp) {
            float a, b2; upk2(aq[rp], a, b2);
            mx = fmaxf(mx, fmaxf(a, b2));
        }
        s.qm[t] = mx;
    }
    // stash k rows
    {
        ull* krow = reinterpret_cast<ull*>(s.kbufT[t]);
#pragma unroll
        for (int rp = 0; rp < 16; ++rp) krow[rp] = ak[rp];
    }
    __syncthreads();

    // ---- logits + softmax: warp h (t<128), lane = row r
    if (t < 128) {
        const int h = t >> 5, r = t & 31;
        float acc = 0.f;
#pragma unroll 8
        for (int d = 0; d < D_; ++d) acc += s.qm[h * D_ + d] * s.kbufT[h * D_ + d][r];
        acc *= 0.0625f;  // C^-0.5
        float mx = acc;
#pragma unroll
        for (int o = 16; o; o >>= 1) mx = fmaxf(mx, __shfl_xor_sync(FULL, mx, o));
        const float e = expf(acc - mx);
        float ss = e;
#pragma unroll
        for (int o = 16; o; o >>= 1) ss += __shfl_xor_sync(FULL, ss, o);
        s.attnw[h][r] = e / ss;
    }
    __syncthreads();

    // ---- attention-weighted sum of V rows (rows still in registers)
    {
        const int h = t >> 6;
        const ull* aw = reinterpret_cast<const ull*>(s.attnw[h]);
        ull o2 = 0ull;
#pragma unroll
        for (int rp = 0; rp < 16; ++rp) fma2(o2, av[rp], aw[rp]);
        float a, b2; upk2(o2, a, b2);
        s.sat[t] = a + b2;
    }
    __syncthreads();

    // ---- proj (warps 0..3, col pairs) and dense branch (warps 4..7, col pairs)
    if (t < 128) {
        const int c0 = 2 * t;
        ull acc = 0ull;
        const float* wp = projw + c0;
#pragma unroll 4
        for (int i = 0; i < C_; ++i) {
            const ull w2 = *reinterpret_cast<const ull*>(wp + (long)i * C_);
            const float sv = s.sat[i];
            fma2(acc, pk2(sv, sv), w2);
        }
        float a, b2; upk2(acc, a, b2);
        s.tmp2[c0]     = fmaxf(a + projb[c0], 0.f);
        s.tmp2[c0 + 1] = fmaxf(b2 + projb[c0 + 1], 0.f);
    } else {
        const int c0 = 2 * (t - 128);
        ull acc = 0ull;
        const float* wd = densew + c0;
#pragma unroll 4
        for (int i = 0; i < CG; ++i) {
            const ull w2 = *reinterpret_cast<const ull*>(wd + (long)i * C_);
            const float gv = s.gmax[i];
            fma2(acc, pk2(gv, gv), w2);
        }
        float a, b2; upk2(acc, a, b2);
        s.tmp2[C_ + c0]     = fmaxf(a + denseb[c0], 0.f);
        s.tmp2[C_ + c0 + 1] = fmaxf(b2 + denseb[c0 + 1], 0.f);
    }
    __syncthreads();
    g_feat_buf[(long)grp * C_ + t] = s.tmp2[t] + s.tmp2[C_ + t];
}

// ============================================================================
// K3: LN2 -> fc1(relu) -> fc2 -> +feat. RPB=16 rows/block, register-tiled:
// thread = (rowgroup q of 4 rows) x (col group cc). Weights load as packed
// ulonglong vectors (direct f32x2 operands), x as pre-duplicated pairs.
// ============================================================================
__global__ void __launch_bounds__(256) mlp_kernel(
    const float* __restrict__ fc1w, const float* __restrict__ fc1b,
    const float* __restrict__ fc2w, const float* __restrict__ fc2b,
    const float* __restrict__ n2g, const float* __restrict__ n2b,
    float* __restrict__ out) {
    ull*   lnDup = reinterpret_cast<ull*>(dynsm);                 // [256][17]
    float* hS    = reinterpret_cast<float*>(dynsm + 256 * 17 * 8); // [16][520]
    const int t = threadIdx.x;
    const long row0 = (long)blockIdx.x * RPB;

    // LN per row: warp w handles rows w and w+8
    {
        const int w = t >> 5, l = t & 31;
        for (int rr = 0; rr < 2; ++rr) {
            const int r = w + 8 * rr;
            const float* frow = g_feat_buf + (row0 + r) * C_;
            float v[8], sum = 0.f;
#pragma unroll
            for (int k = 0; k < 8; ++k) { v[k] = frow[l + 32 * k]; sum += v[k]; }
#pragma unroll
            for (int o = 16; o; o >>= 1) sum += __shfl_xor_sync(FULL, sum, o);
            const float m = sum * (1.f / C_);
            float qv = 0.f;
#pragma unroll
            for (int k = 0; k < 8; ++k) { float d = v[k] - m; qv += d * d; }
#pragma unroll
            for (int o = 16; o; o >>= 1) qv += __shfl_xor_sync(FULL, qv, o);
            const float rs = rsqrtf(qv * (1.f / C_) + 1e-3f);
#pragma unroll
            for (int k = 0; k < 8; ++k) {
                const int i = l + 32 * k;
                const float x = (v[k] - m) * rs * n2g[i] + n2b[i];
                lnDup[i * 17 + r] = pk2(x, x);
            }
        }
    }
    __syncthreads();

    const int q  = t >> 6;   // row group: rows 4q..4q+3
    const int cc = t & 63;

    // fc1: cols cc*8 .. cc*8+7 (4 col-pairs) x 4 rows
    {
        ull acc[4][4];
#pragma unroll
        for (int cp = 0; cp < 4; ++cp)
#pragma unroll
            for (int r = 0; r < 4; ++r) acc[cp][r] = 0ull;
        const float* wbase = fc1w + cc * 8;
#pragma unroll 1
        for (int i = 0; i < C_; ++i) {
            const ulonglong4 wv = *reinterpret_cast<const ulonglong4*>(wbase + (long)i * (2 * C_));
            const ull x0 = lnDup[i * 17 + 4 * q + 0];
            const ull x1 = lnDup[i * 17 + 4 * q + 1];
            const ull x2 = lnDup[i * 17 + 4 * q + 2];
            const ull x3 = lnDup[i * 17 + 4 * q + 3];
            fma2(acc[0][0], wv.x, x0); fma2(acc[0][1], wv.x, x1);
            fma2(acc[0][2], wv.x, x2); fma2(acc[0][3], wv.x, x3);
            fma2(acc[1][0], wv.y, x0); fma2(acc[1][1], wv.y, x1);
            fma2(acc[1][2], wv.y, x2); fma2(acc[1][3], wv.y, x3);
            fma2(acc[2][0], wv.z, x0); fma2(acc[2][1], wv.z, x1);
            fma2(acc[2][2], wv.z, x2); fma2(acc[2][3], wv.z, x3);
            fma2(acc[3][0], wv.w, x0); fma2(acc[3][1], wv.w, x1);
            fma2(acc[3][2], wv.w, x2); fma2(acc[3][3], wv.w, x3);
        }
        const float4 bA = *reinterpret_cast<const float4*>(fc1b + cc * 8);
        const float4 bB = *reinterpret_cast<const float4*>(fc1b + cc * 8 + 4);
        const float bias[8] = {bA.x, bA.y, bA.z, bA.w, bB.x, bB.y, bB.z, bB.w};
#pragma unroll
        for (int cp = 0; cp < 4; ++cp) {
            const int c0 = cc * 8 + 2 * cp;
#pragma unroll
            for (int r = 0; r < 4; ++r) {
                float a, b2; upk2(acc[cp][r], a, b2);
                hS[(4 * q + r) * 520 + c0]     = fmaxf(a + bias[2 * cp], 0.f);
                hS[(4 * q + r) * 520 + c0 + 1] = fmaxf(b2 + bias[2 * cp + 1], 0.f);
            }
        }
    }
    __syncthreads();

    // fc2: cols cc*4 .. cc*4+3 (2 col-pairs) x 4 rows, K=512
    {
        ull acc[2][4];
#pragma unroll
        for (int cp = 0; cp < 2; ++cp)
#pragma unroll
            for (int r = 0; r < 4; ++r) acc[cp][r] = 0ull;
        const float* wbase = fc2w + cc * 4;
#pragma unroll 2
        for (int j = 0; j < 2 * C_; ++j) {
            const ulonglong2 wv = *reinterpret_cast<const ulonglong2*>(wbase + (long)j * C_);
            const float h0 = hS[(4 * q + 0) * 520 + j];
            const float h1 = hS[(4 * q + 1) * 520 + j];
            const float h2 = hS[(4 * q + 2) * 520 + j];
            const float h3 = hS[(4 * q + 3) * 520 + j];
            const ull x0 = pk2(h0, h0), x1 = pk2(h1, h1), x2 = pk2(h2, h2), x3 = pk2(h3, h3);
            fma2(acc[0][0], wv.x, x0); fma2(acc[0][1], wv.x, x1);
            fma2(acc[0][2], wv.x, x2); fma2(acc[0][3], wv.x, x3);
            fma2(acc[1][0], wv.y, x0); fma2(acc[1][1], wv.y, x1);
            fma2(acc[1][2], wv.y, x2); fma2(acc[1][3], wv.y, x3);
        }
        const float4 bias = *reinterpret_cast<const float4*>(fc2b + cc * 4);
#pragma unroll
        for (int r = 0; r < 4; ++r) {
            const long row = row0 + 4 * q + r;
            const float4 res = *reinterpret_cast<const float4*>(g_feat_buf + row * C_ + cc * 4);
            float a0, a1, a2, a3;
            upk2(acc[0][r], a0, a1);
            upk2(acc[1][r], a2, a3);
            float4 o;
            o.x = a0 + bias.x + res.x;
            o.y = a1 + bias.y + res.y;
            o.z = a2 + bias.z + res.z;
            o.w = a3 + bias.w + res.w;
            *reinterpret_cast<float4*>(out + row * C_ + cc * 4) = o;
        }
    }
}

// ============================================================================
extern "C" void kernel_launch(void* const* d_in, const int* in_sizes, int n_in,
                              void* d_out, int out_size) {
    const float* xyz    = (const float*)d_in[0];
    const float* nxyz   = (const float*)d_in[1];
    const float* featin = (const float*)d_in[2];
    const float* wqkv   = (const float*)d_in[3];
    const float* projw  = (const float*)d_in[4];
    const float* projb  = (const float*)d_in[5];
    const float* densew = (const float*)d_in[6];
    const float* denseb = (const float*)d_in[7];
    const float* fc1w   = (const float*)d_in[8];
    const float* fc1b   = (const float*)d_in[9];
    const float* fc2w   = (const float*)d_in[10];
    const float* fc2b   = (const float*)d_in[11];
    const float* n1g    = (const float*)d_in[12];
    const float* n1b    = (const float*)d_in[13];
    const float* n2g    = (const float*)d_in[14];
    const float* n2b    = (const float*)d_in[15];
    float* out = (float*)d_out;

    (void)in_sizes; (void)n_in; (void)out_size;

    const int knn_smem  = N_ * (int)sizeof(float4);            // 64 KB
    const int attn_smem = (int)sizeof(SmemAttn);               // ~58 KB
    const int mlp_smem  = 256 * 17 * 8 + 16 * 520 * 4;         // ~68 KB
    cudaFuncSetAttribute(knn_kernel, cudaFuncAttributeMaxDynamicSharedMemorySize, knn_smem);
    cudaFuncSetAttribute(attn_kernel, cudaFuncAttributeMaxDynamicSharedMemorySize, attn_smem);
    cudaFuncSetAttribute(mlp_kernel, cudaFuncAttributeMaxDynamicSharedMemorySize, mlp_smem);

    knn_kernel<<<dim3(NP_ / 8, B_), 256, knn_smem>>>(xyz, nxyz);
    attn_kernel<<<B_ * NP_, 256, attn_smem>>>(xyz, nxyz, featin, wqkv, projw, projb,
                                              densew, denseb, n1g, n1b);
    mlp_kernel<<<B_ * NP_ / RPB, 256, mlp_smem>>>(fc1w, fc1b, fc2w, fc2b, n2g, n2b, out);
}